// round 2
// baseline (speedup 1.0000x reference)
#include <cuda_runtime.h>
#include <cuda_fp16.h>
#include <mma.h>

using namespace nvcuda;

// Problem shape (fixed by the dataset)
#define MM 4096
#define KK 4096
#define NN 8192

static const int BM = 128;
static const int BN = 128;
static const int BK = 32;
static const int LDA = BK + 8;   // 40 halves (80B rows, 16B-aligned)
static const int LDB = BN + 8;   // 136 halves (272B rows, 16B-aligned)

// Scratch (module-scope device arrays — allowed):
// dense fp16 dequantized weights [K, N] (64 MB) + fp16 copy of x (32 MB)
__device__ __half g_W[(size_t)KK * NN];
__device__ __half g_X[(size_t)MM * KK];

// ---------------------------------------------------------------------------
// Pass 0: convert x fp32 -> fp16 (values are fp16-representable; lossless)
// ---------------------------------------------------------------------------
__global__ void convert_x_kernel(const float* __restrict__ x) {
    size_t i = ((size_t)blockIdx.x * blockDim.x + threadIdx.x) * 8;
    float4 f0 = *reinterpret_cast<const float4*>(x + i);
    float4 f1 = *reinterpret_cast<const float4*>(x + i + 4);
    __half h[8] = {__float2half_rn(f0.x), __float2half_rn(f0.y),
                   __float2half_rn(f0.z), __float2half_rn(f0.w),
                   __float2half_rn(f1.x), __float2half_rn(f1.y),
                   __float2half_rn(f1.z), __float2half_rn(f1.w)};
    *reinterpret_cast<uint4*>(g_X + i) = *reinterpret_cast<uint4*>(h);
}

// ---------------------------------------------------------------------------
// Pass 1: dequantize int4 2:4-sparse weights with group scales -> fp16 dense
// W[k][n] = (q[k][n] - 8) * PATTERNS[meta[k/4][n]][k%4] * scale[k/128][n]
// Pattern masks packed as nibbles (pattern p, row r): bit set if nonzero.
// p0..p5 = 0x3,0x5,0x9,0x6,0xA,0xC  -> lut = 0x00CA6953
// ---------------------------------------------------------------------------
__global__ void dequant_kernel(const int* __restrict__ q,
                               const int* __restrict__ meta,
                               const float* __restrict__ scale) {
    const unsigned lut = 0x00CA6953u;
    const int NV = NN / 8;                     // 1024 vectors of 8 per row
    size_t tid = (size_t)blockIdx.x * blockDim.x + threadIdx.x;
    int k  = (int)(tid >> 10);                 // tid / NV
    int nv = (int)(tid & (NV - 1));
    if (k >= KK) return;
    int n = nv * 8;

    const int4* qv = reinterpret_cast<const int4*>(q + (size_t)k * NN + n);
    int4 q0 = qv[0], q1 = qv[1];
    const int4* mv = reinterpret_cast<const int4*>(meta + (size_t)(k >> 2) * NN + n);
    int4 m0 = mv[0], m1 = mv[1];
    const float4* sv = reinterpret_cast<const float4*>(scale + (size_t)(k >> 7) * NN + n);
    float4 s0 = sv[0], s1 = sv[1];

    int   qq[8] = {q0.x, q0.y, q0.z, q0.w, q1.x, q1.y, q1.z, q1.w};
    int   mm[8] = {m0.x, m0.y, m0.z, m0.w, m1.x, m1.y, m1.z, m1.w};
    float ss[8] = {s0.x, s0.y, s0.z, s0.w, s1.x, s1.y, s1.z, s1.w};
    int r = k & 3;

    __half w[8];
#pragma unroll
    for (int i = 0; i < 8; i++) {
        float mask = (float)((lut >> (mm[i] * 4 + r)) & 1u);
        float val = (float)(qq[i] - 8) * mask * ss[i];
        w[i] = __float2half_rn(val);
    }
    *reinterpret_cast<uint4*>(g_W + (size_t)k * NN + n) = *reinterpret_cast<uint4*>(w);
}

// ---------------------------------------------------------------------------
// Pass 2: fp16 x fp16 -> fp32 accum GEMM, 128x128x32 tiles, cp.async double
// buffer, 8 warps (2x4), warp tile 64x32 (4x2 wmma 16x16x16 fragments).
// Output written as fp32.
// ---------------------------------------------------------------------------
__device__ __forceinline__ void cp_async16(void* sptr, const void* gptr) {
    unsigned a = (unsigned)__cvta_generic_to_shared(sptr);
    asm volatile("cp.async.cg.shared.global [%0], [%1], 16;\n" :: "r"(a), "l"(gptr));
}

__global__ __launch_bounds__(256, 1)
void gemm_kernel(float* __restrict__ out) {
    __shared__ alignas(16) union {
        struct {
            __half A[2][BM * LDA];
            __half B[2][BK * LDB];
        } p;
        float epi[8][256];                  // per-warp 16x16 fp32 staging
    } sm;

    const int bm = blockIdx.y * BM;
    const int bn = blockIdx.x * BN;
    const int tid = threadIdx.x;
    const int warp = tid >> 5;
    const int lane = tid & 31;
    const int wm = warp >> 2;   // 0..1
    const int wn = warp & 3;    // 0..3

    wmma::fragment<wmma::accumulator, 16, 16, 16, float> acc[4][2];
#pragma unroll
    for (int i = 0; i < 4; i++)
#pragma unroll
        for (int j = 0; j < 2; j++)
            wmma::fill_fragment(acc[i][j], 0.0f);

    auto load_stage = [&](int kt, int buf) {
#pragma unroll
        for (int it = 0; it < 2; it++) {
            int v = tid + it * 256;                 // 512 16B vectors per tile
            int ar = v >> 2, ac = (v & 3) * 8;      // A: 128 rows x 32 cols
            cp_async16(&sm.p.A[buf][ar * LDA + ac],
                       g_X + (size_t)(bm + ar) * KK + (size_t)kt * BK + ac);
            int br = v >> 4, bc = (v & 15) * 8;     // B: 32 rows x 128 cols
            cp_async16(&sm.p.B[buf][br * LDB + bc],
                       g_W + (size_t)((size_t)kt * BK + br) * NN + bn + bc);
        }
        asm volatile("cp.async.commit_group;\n");
    };

    load_stage(0, 0);
    asm volatile("cp.async.wait_group 0;\n");
    __syncthreads();

    const int KT = KK / BK;
    int buf = 0;
    for (int kt = 0; kt < KT; kt++) {
        if (kt + 1 < KT) load_stage(kt + 1, buf ^ 1);

#pragma unroll
        for (int kk = 0; kk < BK; kk += 16) {
            wmma::fragment<wmma::matrix_a, 16, 16, 16, __half, wmma::row_major> af[4];
            wmma::fragment<wmma::matrix_b, 16, 16, 16, __half, wmma::row_major> bf[2];
#pragma unroll
            for (int i = 0; i < 4; i++)
                wmma::load_matrix_sync(af[i], &sm.p.A[buf][(wm * 64 + i * 16) * LDA + kk], LDA);
#pragma unroll
            for (int j = 0; j < 2; j++)
                wmma::load_matrix_sync(bf[j], &sm.p.B[buf][kk * LDB + wn * 32 + j * 16], LDB);
#pragma unroll
            for (int i = 0; i < 4; i++)
#pragma unroll
                for (int j = 0; j < 2; j++)
                    wmma::mma_sync(acc[i][j], af[i], bf[j], acc[i][j]);
        }

        asm volatile("cp.async.wait_group 0;\n");
        __syncthreads();
        buf ^= 1;
    }

    // Epilogue: fragments -> smem (fp32) -> fp32 vectorized global stores.
    // All compute done (last __syncthreads above), safe to reuse smem union.
    float* ep = sm.epi[warp];
#pragma unroll
    for (int i = 0; i < 4; i++) {
#pragma unroll
        for (int j = 0; j < 2; j++) {
            wmma::store_matrix_sync(ep, acc[i][j], 16, wmma::mem_row_major);
            __syncwarp();
            int r = lane >> 1;
            int c = (lane & 1) * 8;
            const float* src = ep + r * 16 + c;
            float* dst = out + (size_t)(bm + wm * 64 + i * 16 + r) * NN
                             + bn + wn * 32 + j * 16 + c;
            *reinterpret_cast<float4*>(dst)     = *reinterpret_cast<const float4*>(src);
            *reinterpret_cast<float4*>(dst + 4) = *reinterpret_cast<const float4*>(src + 4);
            __syncwarp();
        }
    }
}

// ---------------------------------------------------------------------------
// Launch. Inputs per metadata order: x (f32), qweight (i32), meta (i32),
// scale (f32). Output: f32 [M, N].
// ---------------------------------------------------------------------------
extern "C" void kernel_launch(void* const* d_in, const int* in_sizes, int n_in,
                              void* d_out, int out_size) {
    (void)in_sizes; (void)n_in; (void)out_size;
    const float* x     = (const float*)d_in[0];
    const int*   qw    = (const int*)d_in[1];
    const int*   meta  = (const int*)d_in[2];
    const float* scale = (const float*)d_in[3];
    float*       out   = (float*)d_out;

    // Pass 0: x fp32 -> fp16 (M*K/8 threads)
    convert_x_kernel<<<(MM * (KK / 8)) / 256, 256>>>(x);

    // Pass 1: dequant (K*N/8 threads)
    dequant_kernel<<<(KK * (NN / 8)) / 256, 256>>>(qw, meta, scale);

    // Pass 2: GEMM
    dim3 grid(NN / BN, MM / BM);             // (64, 32)
    gemm_kernel<<<grid, 256>>>(out);
}

// round 4
// speedup vs baseline: 1.7823x; 1.7823x over previous
#include <cuda_runtime.h>
#include <cuda_fp16.h>
#include <cstdint>

// Problem shape (fixed by the dataset)
#define MM 4096
#define KK 4096
#define NN 8192

// ---------------- GEMM tiling ----------------
#define BM 128
#define BN 256
#define BK 32
#define STAGES 3
#define LDA_SH 40                 // A row stride in halves (32 + 8 pad)
#define LDB_SH 264                // B row stride in halves (256 + 8 pad)
#define AST (BM * LDA_SH * 2)     // 10240 bytes
#define BST (BK * LDB_SH * 2)     // 16896 bytes
#define STB (AST + BST)           // 27136 bytes per stage
#define SMEM_TOTAL (STAGES * STB) // 81408 bytes
#define KT (KK / BK)              // 128 k-iterations

// Scratch (module-scope device arrays — allowed):
// g_W: dequantized dense weights [K, N] fp16 (64MB); g_X: x as fp16 [M, K] (32MB)
__device__ __half g_W[(size_t)KK * NN];
__device__ __half g_X[(size_t)MM * KK];

// ---------------- PTX helpers ----------------
__device__ __forceinline__ void cp16(uint32_t dst, const void* src) {
    asm volatile("cp.async.cg.shared.global [%0], [%1], 16;" :: "r"(dst), "l"(src));
}
__device__ __forceinline__ void cp_commit() { asm volatile("cp.async.commit_group;"); }
template <int N> __device__ __forceinline__ void cp_wait() {
    asm volatile("cp.async.wait_group %0;" :: "n"(N));
}
__device__ __forceinline__ void ldsm_x4(uint32_t* r, uint32_t addr) {
    asm volatile("ldmatrix.sync.aligned.m8n8.x4.shared.b16 {%0,%1,%2,%3}, [%4];"
                 : "=r"(r[0]), "=r"(r[1]), "=r"(r[2]), "=r"(r[3]) : "r"(addr));
}
__device__ __forceinline__ void ldsm_x4_t(uint32_t* r, uint32_t addr) {
    asm volatile("ldmatrix.sync.aligned.m8n8.x4.trans.shared.b16 {%0,%1,%2,%3}, [%4];"
                 : "=r"(r[0]), "=r"(r[1]), "=r"(r[2]), "=r"(r[3]) : "r"(addr));
}
__device__ __forceinline__ void mma16816(float* c, const uint32_t* a, uint32_t b0, uint32_t b1) {
    asm volatile("mma.sync.aligned.m16n8k16.row.col.f32.f16.f16.f32 "
                 "{%0,%1,%2,%3}, {%4,%5,%6,%7}, {%8,%9}, {%0,%1,%2,%3};"
                 : "+f"(c[0]), "+f"(c[1]), "+f"(c[2]), "+f"(c[3])
                 : "r"(a[0]), "r"(a[1]), "r"(a[2]), "r"(a[3]), "r"(b0), "r"(b1));
}

// ---------------------------------------------------------------------------
// Pass 0: convert x fp32 -> fp16 (values fp16-representable; lossless)
// ---------------------------------------------------------------------------
__global__ void convert_x_kernel(const float* __restrict__ x) {
    size_t i = ((size_t)blockIdx.x * blockDim.x + threadIdx.x) * 8;
    float4 f0 = *reinterpret_cast<const float4*>(x + i);
    float4 f1 = *reinterpret_cast<const float4*>(x + i + 4);
    __half h[8] = {__float2half_rn(f0.x), __float2half_rn(f0.y),
                   __float2half_rn(f0.z), __float2half_rn(f0.w),
                   __float2half_rn(f1.x), __float2half_rn(f1.y),
                   __float2half_rn(f1.z), __float2half_rn(f1.w)};
    *reinterpret_cast<uint4*>(g_X + i) = *reinterpret_cast<uint4*>(h);
}

// ---------------------------------------------------------------------------
// Pass 1: dequant int4 2:4-sparse + group scales -> fp16 dense [K, N]
// W[k][n] = (q[k][n] - 8) * PATTERNS[meta[k/4][n]][k%4] * scale[k/128][n]
// Pattern nibbles p0..p5 = 0x3,0x5,0x9,0x6,0xA,0xC -> lut = 0x00CA6953
// ---------------------------------------------------------------------------
__global__ void dequant_kernel(const int* __restrict__ q,
                               const int* __restrict__ meta,
                               const float* __restrict__ scale) {
    const unsigned lut = 0x00CA6953u;
    size_t tid = (size_t)blockIdx.x * blockDim.x + threadIdx.x;
    int k  = (int)(tid >> 10);                 // NN/8 = 1024 vectors per row
    int nv = (int)(tid & 1023);
    if (k >= KK) return;
    int n = nv * 8;

    const int4* qv = (const int4*)(q + (size_t)k * NN + n);
    int4 q0 = qv[0], q1 = qv[1];
    const int4* mv = (const int4*)(meta + (size_t)(k >> 2) * NN + n);
    int4 m0 = mv[0], m1 = mv[1];
    const float4* sv = (const float4*)(scale + (size_t)(k >> 7) * NN + n);
    float4 s0 = sv[0], s1 = sv[1];

    int   qq[8] = {q0.x, q0.y, q0.z, q0.w, q1.x, q1.y, q1.z, q1.w};
    int   mq[8] = {m0.x, m0.y, m0.z, m0.w, m1.x, m1.y, m1.z, m1.w};
    float ss[8] = {s0.x, s0.y, s0.z, s0.w, s1.x, s1.y, s1.z, s1.w};
    int r = k & 3;

    __half w[8];
#pragma unroll
    for (int i = 0; i < 8; i++) {
        float mask = (float)((lut >> (mq[i] * 4 + r)) & 1u);
        w[i] = __float2half_rn((float)(qq[i] - 8) * mask * ss[i]);
    }
    *reinterpret_cast<uint4*>(g_W + (size_t)k * NN + n) = *reinterpret_cast<uint4*>(w);
}

// ---------------------------------------------------------------------------
// Pass 2: mma.sync HMMA GEMM. 128x256x32 CTA tile, 3-stage cp.async ring,
// 8 warps (2x4), 64x64 warp tile, ldmatrix + m16n8k16, fp32 accum, fp32 out.
// ---------------------------------------------------------------------------
__global__ __launch_bounds__(256, 1) void gemm_mma(float* __restrict__ out) {
    extern __shared__ char smem[];
    const uint32_t sb = (uint32_t)__cvta_generic_to_shared(smem);
    const int tid = threadIdx.x;
    const int warp = tid >> 5;
    const int lane = tid & 31;
    const int wm = warp >> 2;      // 0..1 -> M offset 64*wm
    const int wn = warp & 3;       // 0..3 -> N offset 64*wn
    const int bm = blockIdx.x * BM;  // M fastest -> B strip reuse in-wave
    const int bn = blockIdx.y * BN;

    float acc[4][8][4];
#pragma unroll
    for (int i = 0; i < 4; i++)
#pragma unroll
        for (int j = 0; j < 8; j++)
#pragma unroll
            for (int v = 0; v < 4; v++) acc[i][j][v] = 0.0f;

    // ldmatrix base byte offsets within a stage
    const uint32_t a_off = ((uint32_t)(wm * 64 + (lane & 15)) * LDA_SH + (lane >> 4) * 8) * 2;
    const uint32_t b_off = AST + ((uint32_t)(lane & 15) * LDB_SH + wn * 64 + (lane >> 4) * 8) * 2;

    auto load_stage = [&](int kt, int s) {
        uint32_t base = sb + s * STB;
        // A: 128 rows x 4 chunks of 8 halves (512 chunks / 256 threads)
#pragma unroll
        for (int i = 0; i < 2; i++) {
            int c = tid + i * 256;
            int r = c >> 2, kc = (c & 3) * 8;
            cp16(base + ((uint32_t)r * LDA_SH + kc) * 2,
                 g_X + (size_t)(bm + r) * KK + kt * BK + kc);
        }
        // B: 32 rows x 32 chunks of 8 halves (1024 chunks / 256 threads)
#pragma unroll
        for (int i = 0; i < 4; i++) {
            int c = tid + i * 256;
            int r = c >> 5, nc = (c & 31) * 8;
            cp16(base + AST + ((uint32_t)r * LDB_SH + nc) * 2,
                 g_W + (size_t)(kt * BK + r) * NN + bn + nc);
        }
    };

    load_stage(0, 0); cp_commit();
    load_stage(1, 1); cp_commit();

    int s = 0;
#pragma unroll 1
    for (int kt = 0; kt < KT; kt++) {
        cp_wait<1>();          // stage kt resident (2 groups in flight, oldest done)
        __syncthreads();

        if (kt + 2 < KT) load_stage(kt + 2, (s + 2 >= STAGES) ? s + 2 - STAGES : s + 2);
        cp_commit();           // always commit: keeps the 2-in-flight invariant

        uint32_t base = sb + s * STB;
#pragma unroll
        for (int ks = 0; ks < 2; ks++) {
            uint32_t a[4][4], b[4][4];
#pragma unroll
            for (int mi = 0; mi < 4; mi++)
                ldsm_x4(a[mi], base + a_off + ((uint32_t)(mi * 16) * LDA_SH + ks * 16) * 2);
#pragma unroll
            for (int nj = 0; nj < 4; nj++)
                ldsm_x4_t(b[nj], base + b_off + ((uint32_t)(ks * 16) * LDB_SH + nj * 16) * 2);
#pragma unroll
            for (int mi = 0; mi < 4; mi++)
#pragma unroll
                for (int ni = 0; ni < 8; ni++)
                    mma16816(acc[mi][ni], a[mi], b[ni >> 1][(ni & 1) * 2], b[ni >> 1][(ni & 1) * 2 + 1]);
        }
        s = (s + 1 == STAGES) ? 0 : s + 1;
    }

    // Epilogue: direct fp32 stores (thread t owns rows lane/4, lane/4+8; cols (lane%4)*2)
    const int er = lane >> 2;
    const int ec = (lane & 3) * 2;
#pragma unroll
    for (int mi = 0; mi < 4; mi++) {
#pragma unroll
        for (int ni = 0; ni < 8; ni++) {
            size_t row0 = (size_t)(bm + wm * 64 + mi * 16 + er);
            size_t col  = (size_t)(bn + wn * 64 + ni * 8 + ec);
            float2 v0 = make_float2(acc[mi][ni][0], acc[mi][ni][1]);
            float2 v1 = make_float2(acc[mi][ni][2], acc[mi][ni][3]);
            *reinterpret_cast<float2*>(out + row0 * NN + col)       = v0;
            *reinterpret_cast<float2*>(out + (row0 + 8) * NN + col) = v1;
        }
    }
}

// ---------------------------------------------------------------------------
// Launch. Inputs per metadata order: x (f32), qweight (i32), meta (i32),
// scale (f32). Output: f32 [M, N].
// ---------------------------------------------------------------------------
extern "C" void kernel_launch(void* const* d_in, const int* in_sizes, int n_in,
                              void* d_out, int out_size) {
    (void)in_sizes; (void)n_in; (void)out_size;
    const float* x     = (const float*)d_in[0];
    const int*   qw    = (const int*)d_in[1];
    const int*   meta  = (const int*)d_in[2];
    const float* scale = (const float*)d_in[3];
    float*       out   = (float*)d_out;

    cudaFuncSetAttribute(gemm_mma, cudaFuncAttributeMaxDynamicSharedMemorySize, SMEM_TOTAL);

    convert_x_kernel<<<(MM * (KK / 8)) / 256, 256>>>(x);
    dequant_kernel<<<(KK * (NN / 8)) / 256, 256>>>(qw, meta, scale);

    dim3 grid(MM / BM, NN / BN);   // (32, 32), M fastest
    gemm_mma<<<grid, 256, SMEM_TOTAL>>>(out);
}

// round 6
// speedup vs baseline: 2.7316x; 1.5327x over previous
#include <cuda_runtime.h>
#include <cuda_fp16.h>
#include <cstdint>

// Problem shape (fixed by the dataset)
#define MM 4096
#define KK 4096
#define NN 8192

// ---------------- GEMM tiling ----------------
#define BM 128
#define BN 256
#define BK 32
#define STAGES 5
#define LDA_SH 40                 // A row stride in halves (32 + 8 pad)
#define LDB_SH 264                // B row stride in halves (256 + 8 pad)
#define AST (BM * LDA_SH * 2)     // 10240 bytes
#define BST (BK * LDB_SH * 2)     // 16896 bytes
#define STB (AST + BST)           // 27136 bytes per stage
#define SMEM_TOTAL (STAGES * STB) // 135680 bytes
#define KT (KK / BK)              // 128 k-iterations

// Scratch (module-scope device arrays — allowed):
// g_W: dequantized dense weights [K, N] fp16 (64MB); g_X: x as fp16 [M, K] (32MB)
__device__ __half g_W[(size_t)KK * NN];
__device__ __half g_X[(size_t)MM * KK];

// ---------------- PTX helpers ----------------
__device__ __forceinline__ void cp16(uint32_t dst, const void* src) {
    asm volatile("cp.async.cg.shared.global [%0], [%1], 16;" :: "r"(dst), "l"(src));
}
__device__ __forceinline__ void cp_commit() { asm volatile("cp.async.commit_group;"); }
template <int N> __device__ __forceinline__ void cp_wait() {
    asm volatile("cp.async.wait_group %0;" :: "n"(N));
}
__device__ __forceinline__ void ldsm_x4(uint32_t* r, uint32_t addr) {
    asm volatile("ldmatrix.sync.aligned.m8n8.x4.shared.b16 {%0,%1,%2,%3}, [%4];"
                 : "=r"(r[0]), "=r"(r[1]), "=r"(r[2]), "=r"(r[3]) : "r"(addr));
}
__device__ __forceinline__ void ldsm_x4_t(uint32_t* r, uint32_t addr) {
    asm volatile("ldmatrix.sync.aligned.m8n8.x4.trans.shared.b16 {%0,%1,%2,%3}, [%4];"
                 : "=r"(r[0]), "=r"(r[1]), "=r"(r[2]), "=r"(r[3]) : "r"(addr));
}
__device__ __forceinline__ void mma16816(float* c, const uint32_t* a, uint32_t b0, uint32_t b1) {
    asm volatile("mma.sync.aligned.m16n8k16.row.col.f32.f16.f16.f32 "
                 "{%0,%1,%2,%3}, {%4,%5,%6,%7}, {%8,%9}, {%0,%1,%2,%3};"
                 : "+f"(c[0]), "+f"(c[1]), "+f"(c[2]), "+f"(c[3])
                 : "r"(a[0]), "r"(a[1]), "r"(a[2]), "r"(a[3]), "r"(b0), "r"(b1));
}

// ---------------------------------------------------------------------------
// Pass 0: convert x fp32 -> fp16 (values fp16-representable; lossless)
// ---------------------------------------------------------------------------
__global__ void convert_x_kernel(const float* __restrict__ x) {
    size_t i = ((size_t)blockIdx.x * blockDim.x + threadIdx.x) * 8;
    float4 f0 = *reinterpret_cast<const float4*>(x + i);
    float4 f1 = *reinterpret_cast<const float4*>(x + i + 4);
    __half h[8] = {__float2half_rn(f0.x), __float2half_rn(f0.y),
                   __float2half_rn(f0.z), __float2half_rn(f0.w),
                   __float2half_rn(f1.x), __float2half_rn(f1.y),
                   __float2half_rn(f1.z), __float2half_rn(f1.w)};
    *reinterpret_cast<uint4*>(g_X + i) = *reinterpret_cast<uint4*>(h);
}

// ---------------------------------------------------------------------------
// Pass 1: dequant int4 2:4-sparse + group scales -> fp16 dense [K, N]
// W[k][n] = (q[k][n] - 8) * PATTERNS[meta[k/4][n]][k%4] * scale[k/128][n]
// Pattern nibbles p0..p5 = 0x3,0x5,0x9,0x6,0xA,0xC -> lut = 0x00CA6953
// ---------------------------------------------------------------------------
__global__ void dequant_kernel(const int* __restrict__ q,
                               const int* __restrict__ meta,
                               const float* __restrict__ scale) {
    const unsigned lut = 0x00CA6953u;
    size_t tid = (size_t)blockIdx.x * blockDim.x + threadIdx.x;
    int k  = (int)(tid >> 10);                 // NN/8 = 1024 vectors per row
    int nv = (int)(tid & 1023);
    if (k >= KK) return;
    int n = nv * 8;

    const int4* qv = (const int4*)(q + (size_t)k * NN + n);
    int4 q0 = qv[0], q1 = qv[1];
    const int4* mv = (const int4*)(meta + (size_t)(k >> 2) * NN + n);
    int4 m0 = mv[0], m1 = mv[1];
    const float4* sv = (const float4*)(scale + (size_t)(k >> 7) * NN + n);
    float4 s0 = sv[0], s1 = sv[1];

    int   qq[8] = {q0.x, q0.y, q0.z, q0.w, q1.x, q1.y, q1.z, q1.w};
    int   mq[8] = {m0.x, m0.y, m0.z, m0.w, m1.x, m1.y, m1.z, m1.w};
    float ss[8] = {s0.x, s0.y, s0.z, s0.w, s1.x, s1.y, s1.z, s1.w};
    int r = k & 3;

    __half w[8];
#pragma unroll
    for (int i = 0; i < 8; i++) {
        float mask = (float)((lut >> (mq[i] * 4 + r)) & 1u);
        w[i] = __float2half_rn((float)(qq[i] - 8) * mask * ss[i]);
    }
    *reinterpret_cast<uint4*>(g_W + (size_t)k * NN + n) = *reinterpret_cast<uint4*>(w);
}

// ---------------------------------------------------------------------------
// Pass 2: mma.sync HMMA GEMM. 128x256x32 CTA tile, 5-stage cp.async ring,
// cross-iteration fragment double buffering, 8 warps (2x4), 64x64 warp tile.
// Residency invariant: entering iter kt, groups 0..kt+1 (data <= kt+1) are
// complete. Established by prologue cp_wait<2> (4 commits -> groups 0,1 done)
// and maintained by the end-of-iter cp_wait<2> (commits 4+kt+1 -> done kt+2).
// ---------------------------------------------------------------------------
__global__ __launch_bounds__(256, 1) void gemm_mma(float* __restrict__ out) {
    extern __shared__ char smem[];
    const uint32_t sb = (uint32_t)__cvta_generic_to_shared(smem);
    const int tid = threadIdx.x;
    const int warp = tid >> 5;
    const int lane = tid & 31;
    const int wm = warp >> 2;      // 0..1 -> M offset 64*wm
    const int wn = warp & 3;       // 0..3 -> N offset 64*wn
    const int bm = blockIdx.x * BM;  // M fastest -> B strip reuse in-wave
    const int bn = blockIdx.y * BN;

    float acc[4][8][4];
#pragma unroll
    for (int i = 0; i < 4; i++)
#pragma unroll
        for (int j = 0; j < 8; j++)
#pragma unroll
            for (int v = 0; v < 4; v++) acc[i][j][v] = 0.0f;

    // ldmatrix base byte offsets within a stage
    const uint32_t a_off = ((uint32_t)(wm * 64 + (lane & 15)) * LDA_SH + (lane >> 4) * 8) * 2;
    const uint32_t b_off = AST + ((uint32_t)(lane & 15) * LDB_SH + wn * 64 + (lane >> 4) * 8) * 2;

    auto load_stage = [&](int kt, int s) {
        uint32_t base = sb + s * STB;
#pragma unroll
        for (int i = 0; i < 2; i++) {        // A: 512 chunks of 16B
            int c = tid + i * 256;
            int r = c >> 2, kc = (c & 3) * 8;
            cp16(base + ((uint32_t)r * LDA_SH + kc) * 2,
                 g_X + (size_t)(bm + r) * KK + kt * BK + kc);
        }
#pragma unroll
        for (int i = 0; i < 4; i++) {        // B: 1024 chunks of 16B
            int c = tid + i * 256;
            int r = c >> 5, nc = (c & 31) * 8;
            cp16(base + AST + ((uint32_t)r * LDB_SH + nc) * 2,
                 g_W + (size_t)(kt * BK + r) * NN + bn + nc);
        }
    };

    uint32_t af[2][4][4], bf[2][4][4];
    auto ldfrags = [&](int buf, uint32_t stage_base, int ks) {
#pragma unroll
        for (int mi = 0; mi < 4; mi++)
            ldsm_x4(af[buf][mi], stage_base + a_off + ((uint32_t)(mi * 16) * LDA_SH + ks * 16) * 2);
#pragma unroll
        for (int nj = 0; nj < 4; nj++)
            ldsm_x4_t(bf[buf][nj], stage_base + b_off + ((uint32_t)(ks * 16) * LDB_SH + nj * 16) * 2);
    };

    // Prologue: 4 stage loads committed; wait<2> -> stages 0 AND 1 resident
    // (iter 0's ks==1 prefetch reads stage 1 — it must be complete here).
    load_stage(0, 0); cp_commit();
    load_stage(1, 1); cp_commit();
    load_stage(2, 2); cp_commit();
    load_stage(3, 3); cp_commit();
    cp_wait<2>();
    __syncthreads();
    ldfrags(0, sb + 0 * STB, 0);

#pragma unroll 1
    for (int kt = 0; kt < KT; kt++) {
        const int s = kt % STAGES;
        const uint32_t base = sb + s * STB;
        const uint32_t nbase = sb + ((kt + 1) % STAGES) * STB;

#pragma unroll
        for (int ks = 0; ks < 2; ks++) {
            const int cur = ks & 1;
            // Prefetch next slice's fragments (cross-kt at ks==1; stage kt+1
            // is resident per the residency invariant above).
            if (ks == 0)            ldfrags(cur ^ 1, base, 1);
            else if (kt + 1 < KT)   ldfrags(cur ^ 1, nbase, 0);
#pragma unroll
            for (int mi = 0; mi < 4; mi++)
#pragma unroll
                for (int ni = 0; ni < 8; ni++)
                    mma16816(acc[mi][ni], af[cur][mi],
                             bf[cur][ni >> 1][(ni & 1) * 2], bf[cur][ni >> 1][(ni & 1) * 2 + 1]);
        }

        // Refill stage (kt+4)%5 (= (kt-1)%5): its last read was iter kt-1
        // ks==0, ordered before this point by the barrier at end of iter kt-1.
        if (kt + 4 < KT) load_stage(kt + 4, (kt + 4) % STAGES);
        cp_commit();                 // always commit: keeps group-count invariant
        cp_wait<2>();                // data <= kt+2 resident for next iter
        __syncthreads();
    }

    // Epilogue: direct fp32 stores
    const int er = lane >> 2;
    const int ec = (lane & 3) * 2;
#pragma unroll
    for (int mi = 0; mi < 4; mi++) {
#pragma unroll
        for (int ni = 0; ni < 8; ni++) {
            size_t row0 = (size_t)(bm + wm * 64 + mi * 16 + er);
            size_t col  = (size_t)(bn + wn * 64 + ni * 8 + ec);
            float2 v0 = make_float2(acc[mi][ni][0], acc[mi][ni][1]);
            float2 v1 = make_float2(acc[mi][ni][2], acc[mi][ni][3]);
            *reinterpret_cast<float2*>(out + row0 * NN + col)       = v0;
            *reinterpret_cast<float2*>(out + (row0 + 8) * NN + col) = v1;
        }
    }
}

// ---------------------------------------------------------------------------
// Launch. Inputs per metadata order: x (f32), qweight (i32), meta (i32),
// scale (f32). Output: f32 [M, N].
// ---------------------------------------------------------------------------
extern "C" void kernel_launch(void* const* d_in, const int* in_sizes, int n_in,
                              void* d_out, int out_size) {
    (void)in_sizes; (void)n_in; (void)out_size;
    const float* x     = (const float*)d_in[0];
    const int*   qw    = (const int*)d_in[1];
    const int*   meta  = (const int*)d_in[2];
    const float* scale = (const float*)d_in[3];
    float*       out   = (float*)d_out;

    cudaFuncSetAttribute(gemm_mma, cudaFuncAttributeMaxDynamicSharedMemorySize, SMEM_TOTAL);

    convert_x_kernel<<<(MM * (KK / 8)) / 256, 256>>>(x);
    dequant_kernel<<<(KK * (NN / 8)) / 256, 256>>>(qw, meta, scale);

    dim3 grid(MM / BM, NN / BN);   // (32, 32), M fastest
    gemm_mma<<<grid, 256, SMEM_TOTAL>>>(out);
}

// round 7
// speedup vs baseline: 3.0798x; 1.1274x over previous
#include <cuda_runtime.h>
#include <cuda_fp16.h>
#include <cstdint>

// Problem shape (fixed by the dataset)
#define MM 4096
#define KK 4096
#define NN 8192

// ---------------- GEMM tiling (transposed: D[N,M] = Wc[N,K/2]sp x X[K,M]) ----
#define TN 128            // CTA tile over N (mma "M" dim)
#define TM 256            // CTA tile over M (mma "N" dim)
#define BK 64             // real k per stage (2 mma.sp slices of k=32)
#define STAGES 5
#define LDW 40            // Wc smem row stride in halves (32 + 8 pad)
#define WCB (TN * LDW * 2)        // 10240 B
#define XB  (TM * 128)            // 32768 B (XOR-swizzled 128B rows)
#define ECB 1024                  // metadata: 4 k-halves x 64 u32
#define STB (WCB + XB + ECB)      // 44032 B
#define SMEM_TOTAL (STAGES * STB) // 220160 B
#define KT (KK / BK)              // 64 k-iterations

// Scratch (module-scope device arrays — allowed):
__device__ __half   g_Wc[(size_t)NN * (KK / 2)];          // compressed W^T [N][K/2], 32MB
__device__ uint32_t g_Ec[(size_t)(KK / 16) * (NN / 2)];   // paired metadata, 4MB
__device__ __half   g_X[(size_t)MM * KK];                 // x fp16 [M][K], 32MB

// ---------------- PTX helpers ----------------
__device__ __forceinline__ void cp16(uint32_t dst, const void* src) {
    asm volatile("cp.async.cg.shared.global [%0], [%1], 16;" :: "r"(dst), "l"(src));
}
__device__ __forceinline__ void cp_commit() { asm volatile("cp.async.commit_group;"); }
template <int N> __device__ __forceinline__ void cp_wait() {
    asm volatile("cp.async.wait_group %0;" :: "n"(N));
}
__device__ __forceinline__ void ldsm_x4(uint32_t* r, uint32_t addr) {
    asm volatile("ldmatrix.sync.aligned.m8n8.x4.shared.b16 {%0,%1,%2,%3}, [%4];"
                 : "=r"(r[0]), "=r"(r[1]), "=r"(r[2]), "=r"(r[3]) : "r"(addr));
}
// Sparse MMA: D(16x8) += A(16x32, 2:4 sparse, row) * B(32x8, col); metadata e, selector 0
__device__ __forceinline__ void mma_sp(float* c, const uint32_t* a, const uint32_t* b, uint32_t e) {
    asm volatile("mma.sp::ordered_metadata.sync.aligned.m16n8k32.row.col.f32.f16.f16.f32 "
                 "{%0,%1,%2,%3}, {%4,%5,%6,%7}, {%8,%9,%10,%11}, {%0,%1,%2,%3}, %12, 0x0;"
                 : "+f"(c[0]), "+f"(c[1]), "+f"(c[2]), "+f"(c[3])
                 : "r"(a[0]), "r"(a[1]), "r"(a[2]), "r"(a[3]),
                   "r"(b[0]), "r"(b[1]), "r"(b[2]), "r"(b[3]), "r"(e));
}

// ---------------------------------------------------------------------------
// Pass 0: convert x fp32 -> fp16 (values fp16-representable; lossless)
// ---------------------------------------------------------------------------
__global__ void convert_x_kernel(const float* __restrict__ x) {
    size_t i = ((size_t)blockIdx.x * blockDim.x + threadIdx.x) * 8;
    float4 f0 = *reinterpret_cast<const float4*>(x + i);
    float4 f1 = *reinterpret_cast<const float4*>(x + i + 4);
    __half h[8] = {__float2half_rn(f0.x), __float2half_rn(f0.y),
                   __float2half_rn(f0.z), __float2half_rn(f0.w),
                   __float2half_rn(f1.x), __float2half_rn(f1.y),
                   __float2half_rn(f1.z), __float2half_rn(f1.w)};
    *reinterpret_cast<uint4*>(g_X + i) = *reinterpret_cast<uint4*>(h);
}

// ---------------------------------------------------------------------------
// Pass 1: build compressed sparse weights + mma.sp metadata.
// For each (n, k-group of 4): pattern p gives nonzero positions (i0 < i1).
// Compressed value j = (q[4g+ij][n] - 8) * scale;  metadata nibble = i0 | i1<<2.
// Patterns p0..p5 -> (0,1)(0,2)(0,3)(1,2)(1,3)(2,3) -> nibbles 4,8,12,9,13,14
// g_Ec[(k/16)][(n/16)*8 + n%8] = row n bits[0:16) | row n+8 bits[16:32)
// Thread: one n-pair (n, n+8) x 16 k. Grid (KK/64, NN/128), 256 thr.
// ---------------------------------------------------------------------------
__global__ void dequant_sp_kernel(const int* __restrict__ q,
                                  const int* __restrict__ meta,
                                  const float* __restrict__ scale) {
    const unsigned LUT = 0x00ED9C84u;   // nibble per pattern, 4 bits each
    int t = threadIdx.x;
    int k0 = blockIdx.x * 64;
    int n0 = blockIdx.y * 128;
    int kq = t >> 6;                    // 0..3 -> 16-k chunk
    int np = t & 63;                    // n-pair index
    int n  = n0 + (np >> 3) * 16 + (np & 7);
    int kb = k0 + kq * 16;
    float s1 = scale[(size_t)(kb >> 7) * NN + n];
    float s2 = scale[(size_t)(kb >> 7) * NN + n + 8];

    __half w1[8], w2[8];
    unsigned ec = 0;
#pragma unroll
    for (int g = 0; g < 4; g++) {
        int k = kb + g * 4;
        size_t mrow = (size_t)(k >> 2) * NN;
        unsigned nb1 = (LUT >> (meta[mrow + n] * 4)) & 0xFu;
        unsigned nb2 = (LUT >> (meta[mrow + n + 8] * 4)) & 0xFu;
        int a0 = nb1 & 3, a1 = nb1 >> 2;
        int b0 = nb2 & 3, b1 = nb2 >> 2;
        w1[2 * g]     = __float2half_rn((float)(q[(size_t)(k + a0) * NN + n] - 8) * s1);
        w1[2 * g + 1] = __float2half_rn((float)(q[(size_t)(k + a1) * NN + n] - 8) * s1);
        w2[2 * g]     = __float2half_rn((float)(q[(size_t)(k + b0) * NN + n + 8] - 8) * s2);
        w2[2 * g + 1] = __float2half_rn((float)(q[(size_t)(k + b1) * NN + n + 8] - 8) * s2);
        ec |= nb1 << (4 * g);
        ec |= nb2 << (16 + 4 * g);
    }
    *reinterpret_cast<uint4*>(g_Wc + (size_t)n * (KK / 2) + (kb >> 1)) = *reinterpret_cast<uint4*>(w1);
    *reinterpret_cast<uint4*>(g_Wc + (size_t)(n + 8) * (KK / 2) + (kb >> 1)) = *reinterpret_cast<uint4*>(w2);
    g_Ec[(size_t)(kb >> 4) * (NN / 2) + (size_t)(n >> 4) * 8 + (n & 7)] = ec;
}

// ---------------------------------------------------------------------------
// Pass 2: sparse tensor-core GEMM, transposed. 8 warps (wm x wn = 2 x 4),
// warp tile 64n x 64m, 5-stage cp.async ring (R6-proven invariant),
// A(Wc)+metadata fragments double-buffered across k-slices, B(x) per-slice.
// Epilogue: D[n][m] -> smem -> coalesced out[m][n] fp32 stores.
// ---------------------------------------------------------------------------
__global__ __launch_bounds__(256, 1) void gemm_sp(float* __restrict__ out) {
    extern __shared__ char smem[];
    const uint32_t sb = (uint32_t)__cvta_generic_to_shared(smem);
    const int tid = threadIdx.x;
    const int warp = tid >> 5;
    const int lane = tid & 31;
    const int wm = warp >> 2;            // 0..1 over n (64 rows each)
    const int wn = warp & 3;             // 0..3 over m (64 cols each)
    const int n0 = blockIdx.x * TN;
    const int m0 = blockIdx.y * TM;

    float acc[4][8][4];
#pragma unroll
    for (int i = 0; i < 4; i++)
#pragma unroll
        for (int j = 0; j < 8; j++)
#pragma unroll
            for (int v = 0; v < 4; v++) acc[i][j][v] = 0.0f;

    const uint32_t wc_off = ((uint32_t)(wm * 64 + (lane & 15)) * LDW + (lane >> 4) * 8) * 2;
    const int bp = lane >> 3;            // B ldmatrix: k-piece 0..3
    const int brr = lane & 7;            // row within 8 m
    const int eh = lane & 1;             // metadata k-half (valid for T0/T1)

    auto load_stage = [&](int kt, int s) {
        uint32_t base = sb + s * STB;
#pragma unroll
        for (int i = 0; i < 2; i++) {            // Wc: 512 chunks
            int c = tid + i * 256;
            int nr = c >> 2, cc = c & 3;
            cp16(base + (uint32_t)nr * (LDW * 2) + cc * 16,
                 g_Wc + (size_t)(n0 + nr) * (KK / 2) + kt * 32 + cc * 8);
        }
#pragma unroll
        for (int i = 0; i < 8; i++) {            // X: 2048 chunks, XOR swizzle
            int c = tid + i * 256;
            int m = c >> 3, cc = c & 7;
            cp16(base + WCB + (uint32_t)m * 128 + (((uint32_t)(cc ^ (m & 7))) << 4),
                 g_X + (size_t)(m0 + m) * KK + kt * 64 + cc * 8);
        }
        if (tid < 64) {                           // Ec: 64 chunks
            int kh = tid >> 4, cc = tid & 15;
            cp16(base + WCB + XB + (uint32_t)kh * 256 + cc * 16,
                 g_Ec + (size_t)(kt * 4 + kh) * (NN / 2) + (size_t)blockIdx.x * 64 + cc * 4);
        }
    };

    uint32_t af[2][4][4];
    uint32_t ef[2][4];
    auto ldAE = [&](int buf, int s, int ks) {
        uint32_t base = sb + s * STB;
#pragma unroll
        for (int mi = 0; mi < 4; mi++)
            ldsm_x4(af[buf][mi], base + wc_off + ((uint32_t)(mi * 16) * LDW + ks * 16) * 2);
        const uint32_t* Ecs = reinterpret_cast<const uint32_t*>(smem + s * STB + WCB + XB);
#pragma unroll
        for (int mi = 0; mi < 4; mi++)
            ef[buf][mi] = Ecs[(2 * ks + eh) * 64 + wm * 32 + mi * 8 + (lane >> 2)];
    };

    // Prologue (R6 invariant): 4 stage loads committed, wait<2> -> stages 0,1 in
    load_stage(0, 0); cp_commit();
    load_stage(1, 1); cp_commit();
    load_stage(2, 2); cp_commit();
    load_stage(3, 3); cp_commit();
    cp_wait<2>();
    __syncthreads();
    ldAE(0, 0, 0);

#pragma unroll 1
    for (int kt = 0; kt < KT; kt++) {
        const int s = kt % STAGES;
        const int sn = (kt + 1) % STAGES;
        const uint32_t xbase = sb + s * STB + WCB;

#pragma unroll
        for (int ks = 0; ks < 2; ks++) {
            const int cur = ks;
            // Prefetch next slice's A+metadata (stage kt+1 resident per invariant)
            if (ks == 0)           ldAE(1, s, 1);
            else if (kt + 1 < KT)  ldAE(0, sn, 0);

            uint32_t bf[8][4];
#pragma unroll
            for (int ni = 0; ni < 8; ni++) {
                int m = wn * 64 + ni * 8 + brr;
                ldsm_x4(bf[ni], xbase + (uint32_t)m * 128 +
                                (((uint32_t)((ks * 4 + bp) ^ (m & 7))) << 4));
            }
#pragma unroll
            for (int mi = 0; mi < 4; mi++)
#pragma unroll
                for (int ni = 0; ni < 8; ni++)
                    mma_sp(acc[mi][ni], af[cur][mi], bf[ni], ef[cur][mi]);
        }

        if (kt + 4 < KT) load_stage(kt + 4, (kt + 4) % STAGES);
        cp_commit();
        cp_wait<2>();
        __syncthreads();
    }

    // Epilogue: transpose via smem (D[n][m] -> out[m][n]), coalesced stores
    float* D_s = reinterpret_cast<float*>(smem);    // 256 x 132 floats = 132KB
#pragma unroll
    for (int mi = 0; mi < 4; mi++) {
#pragma unroll
        for (int ni = 0; ni < 8; ni++) {
            int ml = wn * 64 + ni * 8 + (lane & 3) * 2;
            int nl = wm * 64 + mi * 16 + (lane >> 2);
            D_s[(size_t)ml * 132 + nl]           = acc[mi][ni][0];
            D_s[(size_t)(ml + 1) * 132 + nl]     = acc[mi][ni][1];
            D_s[(size_t)ml * 132 + nl + 8]       = acc[mi][ni][2];
            D_s[(size_t)(ml + 1) * 132 + nl + 8] = acc[mi][ni][3];
        }
    }
    __syncthreads();
#pragma unroll 4
    for (int i = 0; i < 32; i++) {
        int m = warp * 32 + i;
        float4 v = *reinterpret_cast<const float4*>(&D_s[(size_t)m * 132 + lane * 4]);
        *reinterpret_cast<float4*>(out + (size_t)(m0 + m) * NN + n0 + lane * 4) = v;
    }
}

// ---------------------------------------------------------------------------
// Launch. Inputs per metadata order: x (f32), qweight (i32), meta (i32),
// scale (f32). Output: f32 [M, N].
// ---------------------------------------------------------------------------
extern "C" void kernel_launch(void* const* d_in, const int* in_sizes, int n_in,
                              void* d_out, int out_size) {
    (void)in_sizes; (void)n_in; (void)out_size;
    const float* x     = (const float*)d_in[0];
    const int*   qw    = (const int*)d_in[1];
    const int*   meta  = (const int*)d_in[2];
    const float* scale = (const float*)d_in[3];
    float*       out   = (float*)d_out;

    cudaFuncSetAttribute(gemm_sp, cudaFuncAttributeMaxDynamicSharedMemorySize, SMEM_TOTAL);

    convert_x_kernel<<<(MM * (KK / 8)) / 256, 256>>>(x);

    dim3 dq_grid(KK / 64, NN / 128);     // (64, 64)
    dequant_sp_kernel<<<dq_grid, 256>>>(qw, meta, scale);

    dim3 grid(NN / TN, MM / TM);         // (64, 16), n-block fastest
    gemm_sp<<<grid, 256, SMEM_TOTAL>>>(out);
}